// round 7
// baseline (speedup 1.0000x reference)
#include <cuda_runtime.h>
#include <cstdint>

#define CDIV(a,b) (((a)+(b)-1)/(b))

#define NN 100000
#define NE 1600000
#define SCAN_BS 512
#define NPART ((NN + SCAN_BS - 1) / SCAN_BS)   // 196

// ---------------- device scratch (static; no cudaMalloc) ----------------
__device__ int   g_deg[NN];
__device__ int   g_off[NN + 1];
__device__ int   g_cur[NN];
__device__ int   g_csr[NE];
__device__ int   g_part[256];
__device__ float g_h0 [(size_t)NN * 64];
__device__ float g_h1 [(size_t)NN * 64];

__device__ __forceinline__ const float* sel_buf(int s, const float* ext) {
    return s == 0 ? ext : (s == 1 ? g_h0 : g_h1);
}

// ---------------- bf16 split helpers ----------------
__device__ __forceinline__ void bsplit(float f, uint32_t& hu, float& lo) {
    hu = __float_as_uint(f) & 0xFFFF0000u;
    lo = f - __uint_as_float(hu);
}
__device__ __forceinline__ uint32_t cvt_bf16x2(float hi_elem, float lo_elem) {
    uint32_t r;
    asm("cvt.rn.bf16x2.f32 %0, %1, %2;" : "=r"(r) : "f"(hi_elem), "f"(lo_elem));
    return r;
}
// pack two floats (f0 -> low half = even k, f1 -> high half = odd k) into hi/lo bf16x2
__device__ __forceinline__ void split_pack2(float f0, float f1, uint32_t& hp, uint32_t& lp) {
    uint32_t h0, h1;
    float l0, l1;
    bsplit(f0, h0, l0);
    bsplit(f1, h1, l1);
    hp = (h0 >> 16) | h1;
    lp = cvt_bf16x2(l1, l0);
}

__device__ __forceinline__ void mma_bf16(float* c, const uint32_t* a, uint32_t b0, uint32_t b1) {
    asm volatile(
        "mma.sync.aligned.m16n8k16.row.col.f32.bf16.bf16.f32 "
        "{%0,%1,%2,%3}, {%4,%5,%6,%7}, {%8,%9}, {%0,%1,%2,%3};"
        : "+f"(c[0]), "+f"(c[1]), "+f"(c[2]), "+f"(c[3])
        : "r"(a[0]), "r"(a[1]), "r"(a[2]), "r"(a[3]), "r"(b0), "r"(b1));
}

// ---------------- CSR construction ----------------
__global__ void k_zero_deg() {
    int i = blockIdx.x * blockDim.x + threadIdx.x;
    if (i < NN) g_deg[i] = 0;
}

__global__ void k_count(const int* __restrict__ ei) {
    int e = blockIdx.x * blockDim.x + threadIdx.x;
    if (e < NE) atomicAdd(&g_deg[ei[NE + e]], 1);
}

__global__ void __launch_bounds__(SCAN_BS) k_blocksum() {
    __shared__ int ws[16];
    int i = blockIdx.x * SCAN_BS + threadIdx.x;
    int v = (i < NN) ? g_deg[i] : 0;
    #pragma unroll
    for (int o = 16; o > 0; o >>= 1) v += __shfl_down_sync(0xFFFFFFFFu, v, o);
    int lane = threadIdx.x & 31, wid = threadIdx.x >> 5;
    if (lane == 0) ws[wid] = v;
    __syncthreads();
    if (wid == 0) {
        int s = (lane < 16) ? ws[lane] : 0;
        #pragma unroll
        for (int o = 8; o > 0; o >>= 1) s += __shfl_down_sync(0xFFFFFFFFu, s, o);
        if (lane == 0) g_part[blockIdx.x] = s;
    }
}

__global__ void k_scanpart() {
    __shared__ int sm[256];
    int t = threadIdx.x;
    int v = (t < NPART) ? g_part[t] : 0;
    sm[t] = v;
    __syncthreads();
    #pragma unroll
    for (int o = 1; o < 256; o <<= 1) {
        int u = (t >= o) ? sm[t - o] : 0;
        __syncthreads();
        sm[t] += u;
        __syncthreads();
    }
    if (t < NPART) g_part[t] = sm[t] - v;
}

__global__ void __launch_bounds__(SCAN_BS) k_offsets() {
    __shared__ int ws[16];
    int i = blockIdx.x * SCAN_BS + threadIdx.x;
    int lane = threadIdx.x & 31, wid = threadIdx.x >> 5;
    int v = (i < NN) ? g_deg[i] : 0;
    int incl = v;
    #pragma unroll
    for (int o = 1; o < 32; o <<= 1) {
        int u = __shfl_up_sync(0xFFFFFFFFu, incl, o);
        if (lane >= o) incl += u;
    }
    if (lane == 31) ws[wid] = incl;
    __syncthreads();
    if (wid == 0) {
        int s = (lane < 16) ? ws[lane] : 0;
        int si = s;
        #pragma unroll
        for (int o = 1; o < 32; o <<= 1) {
            int u = __shfl_up_sync(0xFFFFFFFFu, si, o);
            if (lane >= o) si += u;
        }
        if (lane < 16) ws[lane] = si - s;
    }
    __syncthreads();
    if (i < NN) {
        int off = g_part[blockIdx.x] + ws[wid] + incl - v;
        g_off[i] = off;
        g_cur[i] = off;
    }
    if (blockIdx.x == 0 && threadIdx.x == 0) g_off[NN] = NE;
}

__global__ void k_scatter(const int* __restrict__ ei) {
    int e = blockIdx.x * blockDim.x + threadIdx.x;
    if (e < NE) {
        int src = ei[e];
        int dst = ei[NE + e];
        g_csr[atomicAdd(&g_cur[dst], 1)] = src;
    }
}

// ---------------- fused SAGE layer: agg + GEMM + bias + ReLU ----------------
// Block: 256 threads = 8 warps; tile 64(m) x 64(n). KTOT=128 (64 agg | 64 root).
// Phase 1: block gather-means its 64 nodes' neighbors into pre-split bf16x2 smem
//          A0h/A0l[32 k2][64 rows] (exact fragment layout).
// Phase 2: 4 k-tiles of m16n8k16 3-term bf16 split MMA; kt<64 reads prestaged A0
//          (no staging), kt>=64 stages root rows from h. B staged per tile.
// Warp w: rows (w&3)*16..+16, cols (w>>2)*32..+32 (NT=4 n-tiles).
template <bool RELU>
__global__ void __launch_bounds__(256)
k_sage(const float* __restrict__ xext, int hsel, int dsel,
       const float* __restrict__ Wl, const float* __restrict__ Wr,
       const float* __restrict__ bias, float* __restrict__ oext) {
    constexpr int BM  = 64;
    constexpr int LDA = 72;   // 72 mod 32 = 8 -> conflict-free frag loads
    constexpr int LDB = 72;
    __shared__ uint32_t A0h[32][LDA];
    __shared__ uint32_t A0l[32][LDA];
    __shared__ uint32_t A1h[16][LDA];
    __shared__ uint32_t A1l[16][LDA];
    __shared__ uint32_t Bh[16][LDB];
    __shared__ uint32_t Bl[16][LDB];

    const float* __restrict__ h = sel_buf(hsel, xext);
    float* __restrict__ out = (dsel == 1) ? g_h0 : g_h1;

    const int t     = threadIdx.x;
    const int lane  = t & 31;
    const int wid   = t >> 5;
    const int mbase = blockIdx.x * BM;

    // ---- phase 1: aggregate 8 nodes per warp into split smem ----
    {
        const float4* __restrict__ x4 = (const float4*)h;
        int half = lane >> 4;
        int li   = lane & 15;
        #pragma unroll 1
        for (int nn = 0; nn < 8; nn++) {
            int row  = wid * 8 + nn;       // 0..63
            int node = mbase + row;
            float4 acc = make_float4(0.f, 0.f, 0.f, 0.f);
            int beg = 0, end = 0;
            if (node < NN) {
                beg = g_off[node];
                end = g_off[node + 1];
                int e = beg + half;
                #pragma unroll 1
                for (; e + 2 < end; e += 4) {
                    int s0 = g_csr[e];
                    int s1 = g_csr[e + 2];
                    float4 v0 = x4[(size_t)s0 * 16 + li];
                    float4 v1 = x4[(size_t)s1 * 16 + li];
                    acc.x += v0.x + v1.x;
                    acc.y += v0.y + v1.y;
                    acc.z += v0.z + v1.z;
                    acc.w += v0.w + v1.w;
                }
                if (e < end) {
                    int s = g_csr[e];
                    float4 v = x4[(size_t)s * 16 + li];
                    acc.x += v.x; acc.y += v.y; acc.z += v.z; acc.w += v.w;
                }
            }
            acc.x += __shfl_xor_sync(0xFFFFFFFFu, acc.x, 16);
            acc.y += __shfl_xor_sync(0xFFFFFFFFu, acc.y, 16);
            acc.z += __shfl_xor_sync(0xFFFFFFFFu, acc.z, 16);
            acc.w += __shfl_xor_sync(0xFFFFFFFFu, acc.w, 16);
            if (half == 0) {
                int d = end - beg;
                float inv = d > 0 ? 1.f / (float)d : 0.f;
                acc.x *= inv; acc.y *= inv; acc.z *= inv; acc.w *= inv;
                uint32_t hp, lp;
                split_pack2(acc.x, acc.y, hp, lp);
                A0h[2 * li][row] = hp;
                A0l[2 * li][row] = lp;
                split_pack2(acc.z, acc.w, hp, lp);
                A0h[2 * li + 1][row] = hp;
                A0l[2 * li + 1][row] = lp;
            }
        }
    }
    __syncthreads();

    // ---- phase 2: GEMM ----
    const int g     = lane >> 2;
    const int tg    = lane & 3;
    const int mrow  = (wid & 3) * 16;
    const int nbase = (wid >> 2) * 32;
    const int ma    = mrow + g;

    float c[4][4];
    #pragma unroll
    for (int nt = 0; nt < 4; nt++)
        #pragma unroll
        for (int i = 0; i < 4; i++) c[nt][i] = 0.f;

    #pragma unroll 1
    for (int kt = 0; kt < 128; kt += 32) {
        const bool rootHalf = (kt >= 64);
        // stage A1 (root rows) for kt=64,96
        if (rootHalf) {
            #pragma unroll
            for (int idx = t; idx < BM * 16; idx += 256) {
                int row  = idx >> 4;
                int k2   = idx & 15;
                int grow = mbase + row;
                float2 v = make_float2(0.f, 0.f);
                if (grow < NN) v = *(const float2*)&h[(size_t)grow * 64 + (kt - 64) + 2 * k2];
                uint32_t hp, lp;
                split_pack2(v.x, v.y, hp, lp);
                A1h[k2][row] = hp;
                A1l[k2][row] = lp;
            }
        }
        // stage B (Wl for k<64, Wr for k>=64)
        {
            const float* __restrict__ Bsrc = rootHalf ? Wr : Wl;
            const int kb = rootHalf ? (kt - 64) : kt;
            #pragma unroll
            for (int idx = t; idx < 16 * 64; idx += 256) {
                int k2 = idx >> 6;
                int cc = idx & 63;
                float w0 = Bsrc[(size_t)(kb + 2 * k2) * 64 + cc];
                float w1 = Bsrc[(size_t)(kb + 2 * k2 + 1) * 64 + cc];
                uint32_t hp, lp;
                split_pack2(w0, w1, hp, lp);
                Bh[k2][cc] = hp;
                Bl[k2][cc] = lp;
            }
        }
        __syncthreads();

        const uint32_t (*Ah)[LDA] = rootHalf ? A1h : A0h;
        const uint32_t (*Al)[LDA] = rootHalf ? A1l : A0l;
        const int ko = rootHalf ? 0 : (kt >> 1);   // 0 or 16 within A0

        #pragma unroll
        for (int ks = 0; ks < 2; ks++) {
            const int kk = ko + ks * 8 + tg;
            uint32_t ah[4], al[4];
            ah[0] = Ah[kk][ma];      ah[1] = Ah[kk][ma + 8];
            ah[2] = Ah[kk + 4][ma];  ah[3] = Ah[kk + 4][ma + 8];
            al[0] = Al[kk][ma];      al[1] = Al[kk][ma + 8];
            al[2] = Al[kk + 4][ma];  al[3] = Al[kk + 4][ma + 8];
            const int kf = ks * 8 + tg;   // B row within staged tile
            #pragma unroll
            for (int nt = 0; nt < 4; nt++) {
                const int col = nbase + nt * 8 + g;
                uint32_t bh0 = Bh[kf][col];
                uint32_t bh1 = Bh[kf + 4][col];
                uint32_t bl0 = Bl[kf][col];
                uint32_t bl1 = Bl[kf + 4][col];
                mma_bf16(c[nt], al, bh0, bh1);
                mma_bf16(c[nt], ah, bl0, bl1);
                mma_bf16(c[nt], ah, bh0, bh1);
            }
        }
        __syncthreads();
    }

    // epilogue: bias + ReLU, float2 stores
    const int r0 = mbase + mrow + g;
    const int r1 = r0 + 8;
    #pragma unroll
    for (int nt = 0; nt < 4; nt++) {
        const int col = nbase + nt * 8 + 2 * tg;
        float bx = bias[col];
        float by = bias[col + 1];
        if (r0 < NN) {
            float vx = c[nt][0] + bx;
            float vy = c[nt][1] + by;
            if (RELU) { vx = fmaxf(vx, 0.f); vy = fmaxf(vy, 0.f); }
            *(float2*)&out[(size_t)r0 * 64 + col] = make_float2(vx, vy);
        }
        if (r1 < NN) {
            float vx = c[nt][2] + bx;
            float vy = c[nt][3] + by;
            if (RELU) { vx = fmaxf(vx, 0.f); vy = fmaxf(vy, 0.f); }
            *(float2*)&out[(size_t)r1 * 64 + col] = make_float2(vx, vy);
        }
    }
}

// ---------------- final GEMM: out = h0 @ Wlin + blin (K=64, N=32) ----------------
// Block 256 thr = 8 warps, tile 128 x 32; warp w rows w*16..+16, NT=4.
__global__ void __launch_bounds__(256)
k_fin(const float* __restrict__ B0, const float* __restrict__ bias,
      float* __restrict__ out) {
    constexpr int BM   = 128;
    constexpr int LDAP = 136;
    constexpr int LDBP = 40;
    __shared__ uint32_t Ahp[16][LDAP];
    __shared__ uint32_t Alp[16][LDAP];
    __shared__ uint32_t Bhp[16][LDBP];
    __shared__ uint32_t Blp[16][LDBP];

    const float* __restrict__ A = g_h0;
    const int t     = threadIdx.x;
    const int lane  = t & 31;
    const int wid   = t >> 5;
    const int g     = lane >> 2;
    const int tg    = lane & 3;
    const int mbase = blockIdx.x * BM;
    const int ma    = wid * 16 + g;

    float c[4][4];
    #pragma unroll
    for (int nt = 0; nt < 4; nt++)
        #pragma unroll
        for (int i = 0; i < 4; i++) c[nt][i] = 0.f;

    #pragma unroll 1
    for (int kt = 0; kt < 64; kt += 32) {
        #pragma unroll
        for (int idx = t; idx < BM * 16; idx += 256) {
            int row  = idx >> 4;
            int k2   = idx & 15;
            int grow = mbase + row;
            float2 v = make_float2(0.f, 0.f);
            if (grow < NN) v = *(const float2*)&A[(size_t)grow * 64 + kt + 2 * k2];
            uint32_t hp, lp;
            split_pack2(v.x, v.y, hp, lp);
            Ahp[k2][row] = hp;
            Alp[k2][row] = lp;
        }
        #pragma unroll
        for (int idx = t; idx < 16 * 32; idx += 256) {
            int k2 = idx >> 5;
            int cc = idx & 31;
            float w0 = B0[(size_t)(kt + 2 * k2) * 32 + cc];
            float w1 = B0[(size_t)(kt + 2 * k2 + 1) * 32 + cc];
            uint32_t hp, lp;
            split_pack2(w0, w1, hp, lp);
            Bhp[k2][cc] = hp;
            Blp[k2][cc] = lp;
        }
        __syncthreads();

        #pragma unroll
        for (int ks = 0; ks < 2; ks++) {
            const int kk = ks * 8 + tg;
            uint32_t ah[4], al[4];
            ah[0] = Ahp[kk][ma];      ah[1] = Ahp[kk][ma + 8];
            ah[2] = Ahp[kk + 4][ma];  ah[3] = Ahp[kk + 4][ma + 8];
            al[0] = Alp[kk][ma];      al[1] = Alp[kk][ma + 8];
            al[2] = Alp[kk + 4][ma];  al[3] = Alp[kk + 4][ma + 8];
            #pragma unroll
            for (int nt = 0; nt < 4; nt++) {
                const int col = nt * 8 + g;
                uint32_t bh0 = Bhp[kk][col];
                uint32_t bh1 = Bhp[kk + 4][col];
                uint32_t bl0 = Blp[kk][col];
                uint32_t bl1 = Blp[kk + 4][col];
                mma_bf16(c[nt], al, bh0, bh1);
                mma_bf16(c[nt], ah, bl0, bl1);
                mma_bf16(c[nt], ah, bh0, bh1);
            }
        }
        __syncthreads();
    }

    const int r0 = mbase + wid * 16 + g;
    const int r1 = r0 + 8;
    #pragma unroll
    for (int nt = 0; nt < 4; nt++) {
        const int col = nt * 8 + 2 * tg;
        float bx = bias[col];
        float by = bias[col + 1];
        if (r0 < NN)
            *(float2*)&out[(size_t)r0 * 32 + col] = make_float2(c[nt][0] + bx, c[nt][1] + by);
        if (r1 < NN)
            *(float2*)&out[(size_t)r1 * 32 + col] = make_float2(c[nt][2] + bx, c[nt][3] + by);
    }
}

// ---------------- host launcher (pure kernel launches; graph-capturable) ----------------
extern "C" void kernel_launch(void* const* d_in, const int* in_sizes, int n_in,
                              void* d_out, int out_size) {
    const float* x    = (const float*)d_in[0];
    const int*   ei   = (const int*)d_in[1];
    const float* Wl1  = (const float*)d_in[2];
    const float* Wr1  = (const float*)d_in[3];
    const float* b1   = (const float*)d_in[4];
    const float* Wl2  = (const float*)d_in[5];
    const float* Wr2  = (const float*)d_in[6];
    const float* b2   = (const float*)d_in[7];
    const float* Wl3  = (const float*)d_in[8];
    const float* Wr3  = (const float*)d_in[9];
    const float* b3   = (const float*)d_in[10];
    const float* Wlin = (const float*)d_in[11];
    const float* blin = (const float*)d_in[12];
    float*       out  = (float*)d_out;

    // CSR build
    k_zero_deg<<<CDIV(NN, 256), 256>>>();
    k_count<<<CDIV(NE, 256), 256>>>(ei);
    k_blocksum<<<NPART, SCAN_BS>>>();
    k_scanpart<<<1, 256>>>();
    k_offsets<<<NPART, SCAN_BS>>>();
    k_scatter<<<CDIV(NE, 256), 256>>>(ei);

    const int SAGE_BLOCKS = CDIV(NN, 64);
    const int FIN_BLOCKS  = CDIV(NN, 128);

    // fused layers: agg + [agg|h]@[Wl;Wr] + bias + relu
    k_sage<true><<<SAGE_BLOCKS, 256>>>(x, 0, 1, Wl1, Wr1, b1, nullptr);        // x -> h0
    k_sage<true><<<SAGE_BLOCKS, 256>>>(nullptr, 1, 2, Wl2, Wr2, b2, nullptr);  // h0 -> h1
    k_sage<true><<<SAGE_BLOCKS, 256>>>(nullptr, 2, 1, Wl3, Wr3, b3, nullptr);  // h1 -> h0
    // final linear
    k_fin<<<FIN_BLOCKS, 256>>>(Wlin, blin, out);
}

// round 8
// speedup vs baseline: 1.1082x; 1.1082x over previous
#include <cuda_runtime.h>
#include <cuda_fp16.h>
#include <cstdint>

#define CDIV(a,b) (((a)+(b)-1)/(b))

#define NN 100000
#define NE 1600000
#define SCAN_BS 512
#define NPART ((NN + SCAN_BS - 1) / SCAN_BS)   // 196

// ---------------- device scratch (static; no cudaMalloc) ----------------
__device__ int     g_deg[NN];
__device__ int     g_off[NN + 1];
__device__ int     g_cur[NN];
__device__ int     g_csr[NE];
__device__ int     g_part[256];
__device__ float   g_agg[(size_t)NN * 64];
__device__ float   g_h0 [(size_t)NN * 64];
__device__ float   g_h1 [(size_t)NN * 64];
__device__ __half2 g_x16 [(size_t)NN * 32];   // fp16 shadow of gather source
__device__ __half2 g_h16a[(size_t)NN * 32];   // fp16 shadow of h0
__device__ __half2 g_h16b[(size_t)NN * 32];   // fp16 shadow of h1

__device__ __forceinline__ const float* sel_buf(int s, const float* ext) {
    return s == 0 ? ext : (s == 1 ? g_h0 : g_h1);
}

// ---------------- bf16 split helpers (proven R6) ----------------
__device__ __forceinline__ void bsplit(float f, uint32_t& hu, float& lo) {
    hu = __float_as_uint(f) & 0xFFFF0000u;
    lo = f - __uint_as_float(hu);
}
__device__ __forceinline__ uint32_t cvt_bf16x2(float hi_elem, float lo_elem) {
    uint32_t r;
    asm("cvt.rn.bf16x2.f32 %0, %1, %2;" : "=r"(r) : "f"(hi_elem), "f"(lo_elem));
    return r;
}
__device__ __forceinline__ void split_pack2(float f0, float f1, uint32_t& hp, uint32_t& lp) {
    uint32_t h0, h1;
    float l0, l1;
    bsplit(f0, h0, l0);
    bsplit(f1, h1, l1);
    hp = (h0 >> 16) | h1;
    lp = cvt_bf16x2(l1, l0);
}
__device__ __forceinline__ void mma_bf16(float* c, const uint32_t* a, uint32_t b0, uint32_t b1) {
    asm volatile(
        "mma.sync.aligned.m16n8k16.row.col.f32.bf16.bf16.f32 "
        "{%0,%1,%2,%3}, {%4,%5,%6,%7}, {%8,%9}, {%0,%1,%2,%3};"
        : "+f"(c[0]), "+f"(c[1]), "+f"(c[2]), "+f"(c[3])
        : "r"(a[0]), "r"(a[1]), "r"(a[2]), "r"(a[3]), "r"(b0), "r"(b1));
}

// ---------------- CSR construction (R6 proven) ----------------
__global__ void k_zero_deg() {
    int i = blockIdx.x * blockDim.x + threadIdx.x;
    if (i < NN) g_deg[i] = 0;
}

__global__ void k_count(const int* __restrict__ ei) {
    int e = blockIdx.x * blockDim.x + threadIdx.x;
    if (e < NE) atomicAdd(&g_deg[ei[NE + e]], 1);
}

__global__ void __launch_bounds__(SCAN_BS) k_blocksum() {
    __shared__ int ws[16];
    int i = blockIdx.x * SCAN_BS + threadIdx.x;
    int v = (i < NN) ? g_deg[i] : 0;
    #pragma unroll
    for (int o = 16; o > 0; o >>= 1) v += __shfl_down_sync(0xFFFFFFFFu, v, o);
    int lane = threadIdx.x & 31, wid = threadIdx.x >> 5;
    if (lane == 0) ws[wid] = v;
    __syncthreads();
    if (wid == 0) {
        int s = (lane < 16) ? ws[lane] : 0;
        #pragma unroll
        for (int o = 8; o > 0; o >>= 1) s += __shfl_down_sync(0xFFFFFFFFu, s, o);
        if (lane == 0) g_part[blockIdx.x] = s;
    }
}

__global__ void k_scanpart() {
    __shared__ int sm[256];
    int t = threadIdx.x;
    int v = (t < NPART) ? g_part[t] : 0;
    sm[t] = v;
    __syncthreads();
    #pragma unroll
    for (int o = 1; o < 256; o <<= 1) {
        int u = (t >= o) ? sm[t - o] : 0;
        __syncthreads();
        sm[t] += u;
        __syncthreads();
    }
    if (t < NPART) g_part[t] = sm[t] - v;
}

__global__ void __launch_bounds__(SCAN_BS) k_offsets() {
    __shared__ int ws[16];
    int i = blockIdx.x * SCAN_BS + threadIdx.x;
    int lane = threadIdx.x & 31, wid = threadIdx.x >> 5;
    int v = (i < NN) ? g_deg[i] : 0;
    int incl = v;
    #pragma unroll
    for (int o = 1; o < 32; o <<= 1) {
        int u = __shfl_up_sync(0xFFFFFFFFu, incl, o);
        if (lane >= o) incl += u;
    }
    if (lane == 31) ws[wid] = incl;
    __syncthreads();
    if (wid == 0) {
        int s = (lane < 16) ? ws[lane] : 0;
        int si = s;
        #pragma unroll
        for (int o = 1; o < 32; o <<= 1) {
            int u = __shfl_up_sync(0xFFFFFFFFu, si, o);
            if (lane >= o) si += u;
        }
        if (lane < 16) ws[lane] = si - s;
    }
    __syncthreads();
    if (i < NN) {
        int off = g_part[blockIdx.x] + ws[wid] + incl - v;
        g_off[i] = off;
        g_cur[i] = off;
    }
    if (blockIdx.x == 0 && threadIdx.x == 0) g_off[NN] = NE;
}

__global__ void k_scatter(const int* __restrict__ ei) {
    int e = blockIdx.x * blockDim.x + threadIdx.x;
    if (e < NE) {
        int src = ei[e];
        int dst = ei[NE + e];
        g_csr[atomicAdd(&g_cur[dst], 1)] = src;
    }
}

// ---------------- fp32 -> fp16 shadow of x ----------------
__global__ void k_x2h(const float* __restrict__ x) {
    int i = blockIdx.x * blockDim.x + threadIdx.x;
    if (i < NN * 32) {
        float2 v = ((const float2*)x)[i];
        g_x16[i] = __float22half2_rn(v);
    }
}

// ---------------- mean aggregation from fp16 table: quarter-warp per edge ----------------
// warp per node; lanes split into 4 quarters (8 lanes each); per edge a quarter
// reads the full 128B fp16 row (8 x uint4); accumulate fp32; merge via shfl.
__global__ void k_agg16(int xsel) {
    int gw   = (blockIdx.x * blockDim.x + threadIdx.x) >> 5;
    int lane = threadIdx.x & 31;
    if (gw >= NN) return;
    const uint4* __restrict__ t =
        (const uint4*)(xsel == 0 ? g_x16 : (xsel == 1 ? g_h16a : g_h16b));
    int beg = g_off[gw];
    int end = g_off[gw + 1];
    int q  = lane >> 3;      // 0..3: edge slot
    int li = lane & 7;       // 8 channels: li*8 .. li*8+7
    float f0 = 0.f, f1 = 0.f, f2 = 0.f, f3 = 0.f, f4 = 0.f, f5 = 0.f, f6 = 0.f, f7 = 0.f;

    int e = beg + q;
    #pragma unroll 1
    for (; e + 4 < end; e += 8) {
        int s0 = g_csr[e];
        int s1 = g_csr[e + 4];
        uint4 v0 = t[(size_t)s0 * 8 + li];
        uint4 v1 = t[(size_t)s1 * 8 + li];
        float2 a;
        a = __half22float2(*(__half2*)&v0.x); f0 += a.x; f1 += a.y;
        a = __half22float2(*(__half2*)&v0.y); f2 += a.x; f3 += a.y;
        a = __half22float2(*(__half2*)&v0.z); f4 += a.x; f5 += a.y;
        a = __half22float2(*(__half2*)&v0.w); f6 += a.x; f7 += a.y;
        a = __half22float2(*(__half2*)&v1.x); f0 += a.x; f1 += a.y;
        a = __half22float2(*(__half2*)&v1.y); f2 += a.x; f3 += a.y;
        a = __half22float2(*(__half2*)&v1.z); f4 += a.x; f5 += a.y;
        a = __half22float2(*(__half2*)&v1.w); f6 += a.x; f7 += a.y;
    }
    if (e < end) {
        int s = g_csr[e];
        uint4 v = t[(size_t)s * 8 + li];
        float2 a;
        a = __half22float2(*(__half2*)&v.x); f0 += a.x; f1 += a.y;
        a = __half22float2(*(__half2*)&v.y); f2 += a.x; f3 += a.y;
        a = __half22float2(*(__half2*)&v.z); f4 += a.x; f5 += a.y;
        a = __half22float2(*(__half2*)&v.w); f6 += a.x; f7 += a.y;
    }
    // merge quarters: lanes with same li across q
    #pragma unroll
    for (int o = 8; o <= 16; o <<= 1) {
        f0 += __shfl_xor_sync(0xFFFFFFFFu, f0, o);
        f1 += __shfl_xor_sync(0xFFFFFFFFu, f1, o);
        f2 += __shfl_xor_sync(0xFFFFFFFFu, f2, o);
        f3 += __shfl_xor_sync(0xFFFFFFFFu, f3, o);
        f4 += __shfl_xor_sync(0xFFFFFFFFu, f4, o);
        f5 += __shfl_xor_sync(0xFFFFFFFFu, f5, o);
        f6 += __shfl_xor_sync(0xFFFFFFFFu, f6, o);
        f7 += __shfl_xor_sync(0xFFFFFFFFu, f7, o);
    }
    if (q == 0) {
        int d = end - beg;
        float inv = d > 0 ? 1.f / (float)d : 0.f;
        float4* ag = (float4*)g_agg;
        ag[(size_t)gw * 16 + li * 2]     = make_float4(f0 * inv, f1 * inv, f2 * inv, f3 * inv);
        ag[(size_t)gw * 16 + li * 2 + 1] = make_float4(f4 * inv, f5 * inv, f6 * inv, f7 * inv);
    }
}

// ---------------- bf16 3-term split tensor GEMM (R6 proven) + fp16 shadow epilogue ----
template <int KTOT, int NOUT, bool RELU, bool SPLIT>
__global__ void __launch_bounds__(256)
k_gemm(const float* __restrict__ xext, int asel, int dsel,
       const float* __restrict__ B0, const float* __restrict__ B1,
       const float* __restrict__ bias, float* __restrict__ oext, int h16sel) {
    constexpr int BM   = 128;
    constexpr int LDAP = 136;
    constexpr int LDBP = NOUT + 8;
    constexpr int NT   = NOUT / 8;
    __shared__ uint32_t Ahp[16][LDAP];
    __shared__ uint32_t Alp[16][LDAP];
    __shared__ uint32_t Bhp[16][LDBP];
    __shared__ uint32_t Blp[16][LDBP];

    const float* __restrict__ A1 = sel_buf(asel, xext);
    const float* __restrict__ A0 = SPLIT ? (const float*)g_agg : A1;
    float* __restrict__ out = (dsel == 0) ? oext : (dsel == 1 ? g_h0 : g_h1);
    __half2* __restrict__ h16 = (h16sel == 1) ? g_h16a : g_h16b;

    const int t     = threadIdx.x;
    const int lane  = t & 31;
    const int wid   = t >> 5;
    const int g     = lane >> 2;
    const int tg    = lane & 3;
    const int mbase = blockIdx.x * BM;
    const int ma    = wid * 16 + g;

    float c[NT][4];
    #pragma unroll
    for (int nt = 0; nt < NT; nt++)
        #pragma unroll
        for (int i = 0; i < 4; i++) c[nt][i] = 0.f;

    #pragma unroll 1
    for (int kt = 0; kt < KTOT; kt += 32) {
        const bool second = SPLIT && (kt >= 64);
        const float* __restrict__ Asrc = second ? A1 : A0;
        const float* __restrict__ Bsrc = second ? B1 : B0;
        const int kb = second ? (kt - 64) : kt;

        #pragma unroll
        for (int idx = t; idx < BM * 16; idx += 256) {
            int row = idx >> 4;
            int k2  = idx & 15;
            int grow = mbase + row;
            float2 v = make_float2(0.f, 0.f);
            if (grow < NN) v = *(const float2*)&Asrc[(size_t)grow * 64 + kb + 2 * k2];
            uint32_t hp, lp;
            split_pack2(v.x, v.y, hp, lp);
            Ahp[k2][row] = hp;
            Alp[k2][row] = lp;
        }
        #pragma unroll
        for (int idx = t; idx < 16 * NOUT; idx += 256) {
            int k2 = idx / NOUT;
            int cc = idx % NOUT;
            float w0 = Bsrc[(size_t)(kb + 2 * k2) * NOUT + cc];
            float w1 = Bsrc[(size_t)(kb + 2 * k2 + 1) * NOUT + cc];
            uint32_t hp, lp;
            split_pack2(w0, w1, hp, lp);
            Bhp[k2][cc] = hp;
            Blp[k2][cc] = lp;
        }
        __syncthreads();

        #pragma unroll
        for (int ks = 0; ks < 2; ks++) {
            const int kk = ks * 8 + tg;
            uint32_t ah[4], al[4];
            ah[0] = Ahp[kk][ma];      ah[1] = Ahp[kk][ma + 8];
            ah[2] = Ahp[kk + 4][ma];  ah[3] = Ahp[kk + 4][ma + 8];
            al[0] = Alp[kk][ma];      al[1] = Alp[kk][ma + 8];
            al[2] = Alp[kk + 4][ma];  al[3] = Alp[kk + 4][ma + 8];
            #pragma unroll
            for (int nt = 0; nt < NT; nt++) {
                const int col = nt * 8 + g;
                uint32_t bh0 = Bhp[kk][col];
                uint32_t bh1 = Bhp[kk + 4][col];
                uint32_t bl0 = Blp[kk][col];
                uint32_t bl1 = Blp[kk + 4][col];
                mma_bf16(c[nt], al, bh0, bh1);
                mma_bf16(c[nt], ah, bl0, bl1);
                mma_bf16(c[nt], ah, bh0, bh1);
            }
        }
        __syncthreads();
    }

    // epilogue: bias (+ReLU); fp32 stores + optional fp16 shadow stores
    const int r0 = mbase + wid * 16 + g;
    const int r1 = r0 + 8;
    #pragma unroll
    for (int nt = 0; nt < NT; nt++) {
        const int col = nt * 8 + 2 * tg;
        float bx = bias[col];
        float by = bias[col + 1];
        if (r0 < NN) {
            float vx = c[nt][0] + bx;
            float vy = c[nt][1] + by;
            if (RELU) { vx = fmaxf(vx, 0.f); vy = fmaxf(vy, 0.f); }
            *(float2*)&out[(size_t)r0 * NOUT + col] = make_float2(vx, vy);
            if (h16sel) h16[(size_t)r0 * 32 + (col >> 1)] = __float22half2_rn(make_float2(vx, vy));
        }
        if (r1 < NN) {
            float vx = c[nt][2] + bx;
            float vy = c[nt][3] + by;
            if (RELU) { vx = fmaxf(vx, 0.f); vy = fmaxf(vy, 0.f); }
            *(float2*)&out[(size_t)r1 * NOUT + col] = make_float2(vx, vy);
            if (h16sel) h16[(size_t)r1 * 32 + (col >> 1)] = __float22half2_rn(make_float2(vx, vy));
        }
    }
}

// ---------------- host launcher (pure kernel launches; graph-capturable) ----------------
extern "C" void kernel_launch(void* const* d_in, const int* in_sizes, int n_in,
                              void* d_out, int out_size) {
    const float* x    = (const float*)d_in[0];
    const int*   ei   = (const int*)d_in[1];
    const float* Wl1  = (const float*)d_in[2];
    const float* Wr1  = (const float*)d_in[3];
    const float* b1   = (const float*)d_in[4];
    const float* Wl2  = (const float*)d_in[5];
    const float* Wr2  = (const float*)d_in[6];
    const float* b2   = (const float*)d_in[7];
    const float* Wl3  = (const float*)d_in[8];
    const float* Wr3  = (const float*)d_in[9];
    const float* b3   = (const float*)d_in[10];
    const float* Wlin = (const float*)d_in[11];
    const float* blin = (const float*)d_in[12];
    float*       out  = (float*)d_out;

    // CSR build + x fp16 shadow
    k_zero_deg<<<CDIV(NN, 256), 256>>>();
    k_count<<<CDIV(NE, 256), 256>>>(ei);
    k_blocksum<<<NPART, SCAN_BS>>>();
    k_scanpart<<<1, 256>>>();
    k_offsets<<<NPART, SCAN_BS>>>();
    k_scatter<<<CDIV(NE, 256), 256>>>(ei);
    k_x2h<<<CDIV(NN * 32, 256), 256>>>(x);

    const int AGG_BLOCKS  = CDIV(NN, 8);
    const int GEMM_BLOCKS = CDIV(NN, 128);

    // layer 1: agg from x16 -> h0 (+h16a shadow)
    k_agg16<<<AGG_BLOCKS, 256>>>(0);
    k_gemm<128, 64, true, true><<<GEMM_BLOCKS, 256>>>(x, 0, 1, Wl1, Wr1, b1, nullptr, 1);
    // layer 2: agg from h16a -> h1 (+h16b shadow)
    k_agg16<<<AGG_BLOCKS, 256>>>(1);
    k_gemm<128, 64, true, true><<<GEMM_BLOCKS, 256>>>(nullptr, 1, 2, Wl2, Wr2, b2, nullptr, 2);
    // layer 3: agg from h16b -> h0 (no shadow needed)
    k_agg16<<<AGG_BLOCKS, 256>>>(2);
    k_gemm<128, 64, true, true><<<GEMM_BLOCKS, 256>>>(nullptr, 2, 1, Wl3, Wr3, b3, nullptr, 0);
    // final linear
    k_gemm<64, 32, false, false><<<GEMM_BLOCKS, 256>>>(nullptr, 1, 0, Wlin, nullptr, blin, out, 0);
}

// round 9
// speedup vs baseline: 1.2073x; 1.0894x over previous
#include <cuda_runtime.h>
#include <cstdint>

#define CDIV(a,b) (((a)+(b)-1)/(b))

#define NN 100000
#define NE 1600000
#define SCAN_BS 512
#define NPART ((NN + SCAN_BS - 1) / SCAN_BS)   // 196

// ---------------- device scratch (static; no cudaMalloc) ----------------
__device__ int   g_deg[NN];
__device__ int   g_off[NN + 1];
__device__ int   g_pos[NE];
__device__ int   g_csr[NE];
__device__ int   g_part[256];
__device__ float g_agg[(size_t)NN * 64];
__device__ float g_h0 [(size_t)NN * 64];
__device__ float g_h1 [(size_t)NN * 64];

__device__ __forceinline__ const float* sel_buf(int s, const float* ext) {
    return s == 0 ? ext : (s == 1 ? g_h0 : g_h1);
}

// ---------------- bf16 split helpers (R6 proven) ----------------
__device__ __forceinline__ void bsplit(float f, uint32_t& hu, float& lo) {
    hu = __float_as_uint(f) & 0xFFFF0000u;
    lo = f - __uint_as_float(hu);
}
__device__ __forceinline__ uint32_t cvt_bf16x2(float hi_elem, float lo_elem) {
    uint32_t r;
    asm("cvt.rn.bf16x2.f32 %0, %1, %2;" : "=r"(r) : "f"(hi_elem), "f"(lo_elem));
    return r;
}
__device__ __forceinline__ void split_pack2(float f0, float f1, uint32_t& hp, uint32_t& lp) {
    uint32_t h0, h1;
    float l0, l1;
    bsplit(f0, h0, l0);
    bsplit(f1, h1, l1);
    hp = (h0 >> 16) | h1;
    lp = cvt_bf16x2(l1, l0);
}
__device__ __forceinline__ void mma_bf16(float* c, const uint32_t* a, uint32_t b0, uint32_t b1) {
    asm volatile(
        "mma.sync.aligned.m16n8k16.row.col.f32.bf16.bf16.f32 "
        "{%0,%1,%2,%3}, {%4,%5,%6,%7}, {%8,%9}, {%0,%1,%2,%3};"
        : "+f"(c[0]), "+f"(c[1]), "+f"(c[2]), "+f"(c[3])
        : "r"(a[0]), "r"(a[1]), "r"(a[2]), "r"(a[3]), "r"(b0), "r"(b1));
}

// ---------------- CSR construction ----------------
__global__ void k_zero_deg() {
    int i = blockIdx.x * blockDim.x + threadIdx.x;
    if (i < NN) g_deg[i] = 0;
}

// count + record per-edge rank within its destination segment
__global__ void k_count_pos(const int* __restrict__ ei) {
    int e = blockIdx.x * blockDim.x + threadIdx.x;
    if (e < NE) g_pos[e] = atomicAdd(&g_deg[ei[NE + e]], 1);
}

__global__ void __launch_bounds__(SCAN_BS) k_blocksum() {
    __shared__ int ws[16];
    int i = blockIdx.x * SCAN_BS + threadIdx.x;
    int v = (i < NN) ? g_deg[i] : 0;
    #pragma unroll
    for (int o = 16; o > 0; o >>= 1) v += __shfl_down_sync(0xFFFFFFFFu, v, o);
    int lane = threadIdx.x & 31, wid = threadIdx.x >> 5;
    if (lane == 0) ws[wid] = v;
    __syncthreads();
    if (wid == 0) {
        int s = (lane < 16) ? ws[lane] : 0;
        #pragma unroll
        for (int o = 8; o > 0; o >>= 1) s += __shfl_down_sync(0xFFFFFFFFu, s, o);
        if (lane == 0) g_part[blockIdx.x] = s;
    }
}

__global__ void k_scanpart() {
    __shared__ int sm[256];
    int t = threadIdx.x;
    int v = (t < NPART) ? g_part[t] : 0;
    sm[t] = v;
    __syncthreads();
    #pragma unroll
    for (int o = 1; o < 256; o <<= 1) {
        int u = (t >= o) ? sm[t - o] : 0;
        __syncthreads();
        sm[t] += u;
        __syncthreads();
    }
    if (t < NPART) g_part[t] = sm[t] - v;
}

__global__ void __launch_bounds__(SCAN_BS) k_offsets() {
    __shared__ int ws[16];
    int i = blockIdx.x * SCAN_BS + threadIdx.x;
    int lane = threadIdx.x & 31, wid = threadIdx.x >> 5;
    int v = (i < NN) ? g_deg[i] : 0;
    int incl = v;
    #pragma unroll
    for (int o = 1; o < 32; o <<= 1) {
        int u = __shfl_up_sync(0xFFFFFFFFu, incl, o);
        if (lane >= o) incl += u;
    }
    if (lane == 31) ws[wid] = incl;
    __syncthreads();
    if (wid == 0) {
        int s = (lane < 16) ? ws[lane] : 0;
        int si = s;
        #pragma unroll
        for (int o = 1; o < 32; o <<= 1) {
            int u = __shfl_up_sync(0xFFFFFFFFu, si, o);
            if (lane >= o) si += u;
        }
        if (lane < 16) ws[lane] = si - s;
    }
    __syncthreads();
    if (i < NN) g_off[i] = g_part[blockIdx.x] + ws[wid] + incl - v;
    if (blockIdx.x == 0 && threadIdx.x == 0) g_off[NN] = NE;
}

// atomic-free scatter using precomputed ranks
__global__ void k_scatter2(const int* __restrict__ ei) {
    int e = blockIdx.x * blockDim.x + threadIdx.x;
    if (e < NE) {
        int src = ei[e];
        int dst = ei[NE + e];
        g_csr[g_off[dst] + g_pos[e]] = src;
    }
}

// ---------------- mean aggregation: warp per node, half-warp per edge, deep unroll ----
__global__ void k_agg(const float* __restrict__ xext, int xsel) {
    int gw   = (blockIdx.x * blockDim.x + threadIdx.x) >> 5;
    int lane = threadIdx.x & 31;
    if (gw >= NN) return;
    const float* __restrict__ x = sel_buf(xsel, xext);
    const float4* __restrict__ x4 = (const float4*)x;
    int beg = g_off[gw];
    int end = g_off[gw + 1];
    int half = lane >> 4;
    int li   = lane & 15;
    float4 acc = make_float4(0.f, 0.f, 0.f, 0.f);
    int e = beg + half;
    // 4 edges in flight per half-warp (8 per warp)
    #pragma unroll 1
    for (; e + 6 < end; e += 8) {
        int s0 = g_csr[e];
        int s1 = g_csr[e + 2];
        int s2 = g_csr[e + 4];
        int s3 = g_csr[e + 6];
        float4 v0 = x4[(size_t)s0 * 16 + li];
        float4 v1 = x4[(size_t)s1 * 16 + li];
        float4 v2 = x4[(size_t)s2 * 16 + li];
        float4 v3 = x4[(size_t)s3 * 16 + li];
        acc.x += (v0.x + v1.x) + (v2.x + v3.x);
        acc.y += (v0.y + v1.y) + (v2.y + v3.y);
        acc.z += (v0.z + v1.z) + (v2.z + v3.z);
        acc.w += (v0.w + v1.w) + (v2.w + v3.w);
    }
    #pragma unroll 1
    for (; e < end; e += 2) {
        int s = g_csr[e];
        float4 v = x4[(size_t)s * 16 + li];
        acc.x += v.x; acc.y += v.y; acc.z += v.z; acc.w += v.w;
    }
    acc.x += __shfl_xor_sync(0xFFFFFFFFu, acc.x, 16);
    acc.y += __shfl_xor_sync(0xFFFFFFFFu, acc.y, 16);
    acc.z += __shfl_xor_sync(0xFFFFFFFFu, acc.z, 16);
    acc.w += __shfl_xor_sync(0xFFFFFFFFu, acc.w, 16);
    if (half == 0) {
        int d = end - beg;
        float inv = d > 0 ? 1.f / (float)d : 0.f;
        acc.x *= inv; acc.y *= inv; acc.z *= inv; acc.w *= inv;
        ((float4*)g_agg)[(size_t)gw * 16 + li] = acc;
    }
}

// ---------------- bf16 3-term split tensor GEMM, optional fused final linear ----------
// Main: out = relu([agg | A1] @ [B0;B1] + bias). Block 256 thr, tile 128 x 64.
// If FUSE_FIN: instead of storing h, re-split relu'd fragments into smem and run
// h @ Wfin + bfin (K=64, N=32), storing the 100k x 32 result directly.
template <bool FUSE_FIN>
__global__ void __launch_bounds__(256)
k_gemm(const float* __restrict__ xext, int asel, int dsel,
       const float* __restrict__ B0, const float* __restrict__ B1,
       const float* __restrict__ bias,
       const float* __restrict__ Wfin, const float* __restrict__ bfin,
       float* __restrict__ oext) {
    constexpr int BM   = 128;
    constexpr int LDAP = 136;
    constexpr int LDBP = 72;
    constexpr int MAIN_SZ = 2 * 16 * LDAP + 2 * 16 * LDBP;            // 6656
    constexpr int FIN_SZ  = 2 * 32 * LDAP + 2 * 32 * 40;              // 11264
    constexpr int BUF_SZ  = FUSE_FIN ? (FIN_SZ > MAIN_SZ ? FIN_SZ : MAIN_SZ) : MAIN_SZ;
    __shared__ uint32_t buf[BUF_SZ];

    uint32_t (*Ahp)[LDAP] = (uint32_t(*)[LDAP])(buf);
    uint32_t (*Alp)[LDAP] = (uint32_t(*)[LDAP])(buf + 16 * LDAP);
    uint32_t (*Bhp)[LDBP] = (uint32_t(*)[LDBP])(buf + 2 * 16 * LDAP);
    uint32_t (*Blp)[LDBP] = (uint32_t(*)[LDBP])(buf + 2 * 16 * LDAP + 16 * LDBP);

    const float* __restrict__ A1 = sel_buf(asel, xext);
    const float* __restrict__ A0 = (const float*)g_agg;
    float* __restrict__ out = FUSE_FIN ? oext : (dsel == 1 ? g_h0 : g_h1);

    const int t     = threadIdx.x;
    const int lane  = t & 31;
    const int wid   = t >> 5;
    const int g     = lane >> 2;
    const int tg    = lane & 3;
    const int mbase = blockIdx.x * BM;
    const int ma    = wid * 16 + g;

    float c[8][4];
    #pragma unroll
    for (int nt = 0; nt < 8; nt++)
        #pragma unroll
        for (int i = 0; i < 4; i++) c[nt][i] = 0.f;

    #pragma unroll 1
    for (int kt = 0; kt < 128; kt += 32) {
        const bool second = (kt >= 64);
        const float* __restrict__ Asrc = second ? A1 : A0;
        const float* __restrict__ Bsrc = second ? B1 : B0;
        const int kb = second ? (kt - 64) : kt;

        #pragma unroll
        for (int idx = t; idx < BM * 16; idx += 256) {
            int row = idx >> 4;
            int k2  = idx & 15;
            int grow = mbase + row;
            float2 v = make_float2(0.f, 0.f);
            if (grow < NN) v = *(const float2*)&Asrc[(size_t)grow * 64 + kb + 2 * k2];
            uint32_t hp, lp;
            split_pack2(v.x, v.y, hp, lp);
            Ahp[k2][row] = hp;
            Alp[k2][row] = lp;
        }
        #pragma unroll
        for (int idx = t; idx < 16 * 64; idx += 256) {
            int k2 = idx >> 6;
            int cc = idx & 63;
            float w0 = Bsrc[(size_t)(kb + 2 * k2) * 64 + cc];
            float w1 = Bsrc[(size_t)(kb + 2 * k2 + 1) * 64 + cc];
            uint32_t hp, lp;
            split_pack2(w0, w1, hp, lp);
            Bhp[k2][cc] = hp;
            Blp[k2][cc] = lp;
        }
        __syncthreads();

        #pragma unroll
        for (int ks = 0; ks < 2; ks++) {
            const int kk = ks * 8 + tg;
            uint32_t ah[4], al[4];
            ah[0] = Ahp[kk][ma];      ah[1] = Ahp[kk][ma + 8];
            ah[2] = Ahp[kk + 4][ma];  ah[3] = Ahp[kk + 4][ma + 8];
            al[0] = Alp[kk][ma];      al[1] = Alp[kk][ma + 8];
            al[2] = Alp[kk + 4][ma];  al[3] = Alp[kk + 4][ma + 8];
            #pragma unroll
            for (int nt = 0; nt < 8; nt++) {
                const int col = nt * 8 + g;
                uint32_t bh0 = Bhp[kk][col];
                uint32_t bh1 = Bhp[kk + 4][col];
                uint32_t bl0 = Blp[kk][col];
                uint32_t bl1 = Blp[kk + 4][col];
                mma_bf16(c[nt], al, bh0, bh1);
                mma_bf16(c[nt], ah, bl0, bl1);
                mma_bf16(c[nt], ah, bh0, bh1);
            }
        }
        __syncthreads();
    }

    const int r0 = mbase + wid * 16 + g;
    const int r1 = r0 + 8;

    if constexpr (!FUSE_FIN) {
        // epilogue: bias + ReLU, float2 stores
        #pragma unroll
        for (int nt = 0; nt < 8; nt++) {
            const int col = nt * 8 + 2 * tg;
            float bx = bias[col];
            float by = bias[col + 1];
            if (r0 < NN) {
                float vx = fmaxf(c[nt][0] + bx, 0.f);
                float vy = fmaxf(c[nt][1] + by, 0.f);
                *(float2*)&out[(size_t)r0 * 64 + col] = make_float2(vx, vy);
            }
            if (r1 < NN) {
                float vx = fmaxf(c[nt][2] + bx, 0.f);
                float vy = fmaxf(c[nt][3] + by, 0.f);
                *(float2*)&out[(size_t)r1 * 64 + col] = make_float2(vx, vy);
            }
        }
    } else {
        // fused final stage: h fragments (bias+relu) -> split smem -> h @ Wfin + bfin
        uint32_t (*Fh)[LDAP]  = (uint32_t(*)[LDAP])(buf);
        uint32_t (*Fl)[LDAP]  = (uint32_t(*)[LDAP])(buf + 32 * LDAP);
        uint32_t (*B2h)[40]   = (uint32_t(*)[40])(buf + 2 * 32 * LDAP);
        uint32_t (*B2l)[40]   = (uint32_t(*)[40])(buf + 2 * 32 * LDAP + 32 * 40);

        const int rl0 = wid * 16 + g;      // local rows
        const int rl1 = rl0 + 8;
        #pragma unroll
        for (int nt = 0; nt < 8; nt++) {
            const int col = nt * 8 + 2 * tg;
            const int k2  = nt * 4 + tg;   // col/2
            float bx = bias[col];
            float by = bias[col + 1];
            float v0x = fmaxf(c[nt][0] + bx, 0.f);
            float v0y = fmaxf(c[nt][1] + by, 0.f);
            float v1x = fmaxf(c[nt][2] + bx, 0.f);
            float v1y = fmaxf(c[nt][3] + by, 0.f);
            uint32_t hp, lp;
            split_pack2(v0x, v0y, hp, lp);
            Fh[k2][rl0] = hp;
            Fl[k2][rl0] = lp;
            split_pack2(v1x, v1y, hp, lp);
            Fh[k2][rl1] = hp;
            Fl[k2][rl1] = lp;
        }
        // stage Wfin (64 x 32) split
        #pragma unroll
        for (int idx = t; idx < 32 * 32; idx += 256) {
            int k2 = idx >> 5;
            int cc = idx & 31;
            float w0 = Wfin[(size_t)(2 * k2) * 32 + cc];
            float w1 = Wfin[(size_t)(2 * k2 + 1) * 32 + cc];
            uint32_t hp, lp;
            split_pack2(w0, w1, hp, lp);
            B2h[k2][cc] = hp;
            B2l[k2][cc] = lp;
        }
        __syncthreads();

        float c2[4][4];
        #pragma unroll
        for (int nt = 0; nt < 4; nt++)
            #pragma unroll
            for (int i = 0; i < 4; i++) c2[nt][i] = 0.f;

        #pragma unroll
        for (int ks = 0; ks < 4; ks++) {
            const int kk = ks * 8 + tg;
            uint32_t ah[4], al[4];
            ah[0] = Fh[kk][ma];      ah[1] = Fh[kk][ma + 8];
            ah[2] = Fh[kk + 4][ma];  ah[3] = Fh[kk + 4][ma + 8];
            al[0] = Fl[kk][ma];      al[1] = Fl[kk][ma + 8];
            al[2] = Fl[kk + 4][ma];  al[3] = Fl[kk + 4][ma + 8];
            #pragma unroll
            for (int nt = 0; nt < 4; nt++) {
                const int col = nt * 8 + g;
                uint32_t bh0 = B2h[kk][col];
                uint32_t bh1 = B2h[kk + 4][col];
                uint32_t bl0 = B2l[kk][col];
                uint32_t bl1 = B2l[kk + 4][col];
                mma_bf16(c2[nt], al, bh0, bh1);
                mma_bf16(c2[nt], ah, bl0, bl1);
                mma_bf16(c2[nt], ah, bh0, bh1);
            }
        }

        #pragma unroll
        for (int nt = 0; nt < 4; nt++) {
            const int col = nt * 8 + 2 * tg;
            float bx = bfin[col];
            float by = bfin[col + 1];
            if (r0 < NN)
                *(float2*)&out[(size_t)r0 * 32 + col] = make_float2(c2[nt][0] + bx, c2[nt][1] + by);
            if (r1 < NN)
                *(float2*)&out[(size_t)r1 * 32 + col] = make_float2(c2[nt][2] + bx, c2[nt][3] + by);
        }
    }
}

// ---------------- host launcher (pure kernel launches; graph-capturable) ----------------
extern "C" void kernel_launch(void* const* d_in, const int* in_sizes, int n_in,
                              void* d_out, int out_size) {
    const float* x    = (const float*)d_in[0];
    const int*   ei   = (const int*)d_in[1];
    const float* Wl1  = (const float*)d_in[2];
    const float* Wr1  = (const float*)d_in[3];
    const float* b1   = (const float*)d_in[4];
    const float* Wl2  = (const float*)d_in[5];
    const float* Wr2  = (const float*)d_in[6];
    const float* b2   = (const float*)d_in[7];
    const float* Wl3  = (const float*)d_in[8];
    const float* Wr3  = (const float*)d_in[9];
    const float* b3   = (const float*)d_in[10];
    const float* Wlin = (const float*)d_in[11];
    const float* blin = (const float*)d_in[12];
    float*       out  = (float*)d_out;

    // CSR build (atomic-free scatter via pos array)
    k_zero_deg<<<CDIV(NN, 256), 256>>>();
    k_count_pos<<<CDIV(NE, 256), 256>>>(ei);
    k_blocksum<<<NPART, SCAN_BS>>>();
    k_scanpart<<<1, 256>>>();
    k_offsets<<<NPART, SCAN_BS>>>();
    k_scatter2<<<CDIV(NE, 256), 256>>>(ei);

    const int AGG_BLOCKS  = CDIV(NN, 8);
    const int GEMM_BLOCKS = CDIV(NN, 128);

    // layer 1: x -> h0
    k_agg<<<AGG_BLOCKS, 256>>>(x, 0);
    k_gemm<false><<<GEMM_BLOCKS, 256>>>(x, 0, 1, Wl1, Wr1, b1, nullptr, nullptr, nullptr);
    // layer 2: h0 -> h1
    k_agg<<<AGG_BLOCKS, 256>>>(nullptr, 1);
    k_gemm<false><<<GEMM_BLOCKS, 256>>>(nullptr, 1, 2, Wl2, Wr2, b2, nullptr, nullptr, nullptr);
    // layer 3 + final linear fused: h1 -> out
    k_agg<<<AGG_BLOCKS, 256>>>(nullptr, 2);
    k_gemm<true><<<GEMM_BLOCKS, 256>>>(nullptr, 2, 0, Wl3, Wr3, b3, Wlin, blin, out);
}

// round 10
// speedup vs baseline: 1.2156x; 1.0069x over previous
#include <cuda_runtime.h>
#include <cstdint>

#define CDIV(a,b) (((a)+(b)-1)/(b))

#define NN 100000
#define NE 1600000
#define SCAN_BS 512
#define NPART ((NN + SCAN_BS - 1) / SCAN_BS)   // 196

// ---------------- device scratch (static; no cudaMalloc) ----------------
__device__ int   g_deg[NN];
__device__ int   g_off[NN + 1];
__device__ int   g_pos[NE];
__device__ int   g_csr[NE];
__device__ int   g_part[256];
__device__ float g_agg[(size_t)NN * 64];
__device__ float g_h0 [(size_t)NN * 64];
__device__ float g_h1 [(size_t)NN * 64];

__device__ __forceinline__ const float* sel_buf(int s, const float* ext) {
    return s == 0 ? ext : (s == 1 ? g_h0 : g_h1);
}

// ---------------- bf16 split helpers (R6 proven) ----------------
__device__ __forceinline__ void bsplit(float f, uint32_t& hu, float& lo) {
    hu = __float_as_uint(f) & 0xFFFF0000u;
    lo = f - __uint_as_float(hu);
}
__device__ __forceinline__ uint32_t cvt_bf16x2(float hi_elem, float lo_elem) {
    uint32_t r;
    asm("cvt.rn.bf16x2.f32 %0, %1, %2;" : "=r"(r) : "f"(hi_elem), "f"(lo_elem));
    return r;
}
__device__ __forceinline__ void split_pack2(float f0, float f1, uint32_t& hp, uint32_t& lp) {
    uint32_t h0, h1;
    float l0, l1;
    bsplit(f0, h0, l0);
    bsplit(f1, h1, l1);
    hp = (h0 >> 16) | h1;
    lp = cvt_bf16x2(l1, l0);
}
__device__ __forceinline__ void mma_bf16(float* c, const uint32_t* a, uint32_t b0, uint32_t b1) {
    asm volatile(
        "mma.sync.aligned.m16n8k16.row.col.f32.bf16.bf16.f32 "
        "{%0,%1,%2,%3}, {%4,%5,%6,%7}, {%8,%9}, {%0,%1,%2,%3};"
        : "+f"(c[0]), "+f"(c[1]), "+f"(c[2]), "+f"(c[3])
        : "r"(a[0]), "r"(a[1]), "r"(a[2]), "r"(a[3]), "r"(b0), "r"(b1));
}

// ---------------- CSR construction ----------------
__global__ void k_zero_deg() {
    int i = blockIdx.x * blockDim.x + threadIdx.x;
    if (i < NN) g_deg[i] = 0;
}

__global__ void k_count_pos(const int* __restrict__ ei) {
    int e = blockIdx.x * blockDim.x + threadIdx.x;
    if (e < NE) g_pos[e] = atomicAdd(&g_deg[ei[NE + e]], 1);
}

// per-block raw sums of degrees (no global scan pass needed)
__global__ void __launch_bounds__(SCAN_BS) k_blocksum() {
    __shared__ int ws[16];
    int i = blockIdx.x * SCAN_BS + threadIdx.x;
    int v = (i < NN) ? g_deg[i] : 0;
    #pragma unroll
    for (int o = 16; o > 0; o >>= 1) v += __shfl_down_sync(0xFFFFFFFFu, v, o);
    int lane = threadIdx.x & 31, wid = threadIdx.x >> 5;
    if (lane == 0) ws[wid] = v;
    __syncthreads();
    if (wid == 0) {
        int s = (lane < 16) ? ws[lane] : 0;
        #pragma unroll
        for (int o = 8; o > 0; o >>= 1) s += __shfl_down_sync(0xFFFFFFFFu, s, o);
        if (lane == 0) g_part[blockIdx.x] = s;
    }
}

// offsets: in-block scan + warp-1 computes base = sum of preceding block partials
__global__ void __launch_bounds__(SCAN_BS) k_offsets() {
    __shared__ int ws[16];
    __shared__ int sbase;
    int i = blockIdx.x * SCAN_BS + threadIdx.x;
    int lane = threadIdx.x & 31, wid = threadIdx.x >> 5;

    if (wid == 1) {   // base over g_part[0..bid)
        int acc = 0;
        for (int j = lane; j < blockIdx.x; j += 32) acc += g_part[j];
        #pragma unroll
        for (int o = 16; o > 0; o >>= 1) acc += __shfl_down_sync(0xFFFFFFFFu, acc, o);
        if (lane == 0) sbase = acc;
    }

    int v = (i < NN) ? g_deg[i] : 0;
    int incl = v;
    #pragma unroll
    for (int o = 1; o < 32; o <<= 1) {
        int u = __shfl_up_sync(0xFFFFFFFFu, incl, o);
        if (lane >= o) incl += u;
    }
    if (lane == 31) ws[wid] = incl;
    __syncthreads();
    if (wid == 0) {
        int s = (lane < 16) ? ws[lane] : 0;
        int si = s;
        #pragma unroll
        for (int o = 1; o < 32; o <<= 1) {
            int u = __shfl_up_sync(0xFFFFFFFFu, si, o);
            if (lane >= o) si += u;
        }
        if (lane < 16) ws[lane] = si - s;
    }
    __syncthreads();
    if (i < NN) g_off[i] = sbase + ws[wid] + incl - v;
    if (blockIdx.x == 0 && threadIdx.x == 0) g_off[NN] = NE;
}

__global__ void k_scatter2(const int* __restrict__ ei) {
    int e = blockIdx.x * blockDim.x + threadIdx.x;
    if (e < NE) {
        int src = ei[e];
        int dst = ei[NE + e];
        g_csr[g_off[dst] + g_pos[e]] = src;
    }
}

// ---------------- mean aggregation (R9 proven) ----------------
__global__ void k_agg(const float* __restrict__ xext, int xsel) {
    int gw   = (blockIdx.x * blockDim.x + threadIdx.x) >> 5;
    int lane = threadIdx.x & 31;
    if (gw >= NN) return;
    const float* __restrict__ x = sel_buf(xsel, xext);
    const float4* __restrict__ x4 = (const float4*)x;
    int beg = g_off[gw];
    int end = g_off[gw + 1];
    int half = lane >> 4;
    int li   = lane & 15;
    float4 acc = make_float4(0.f, 0.f, 0.f, 0.f);
    int e = beg + half;
    #pragma unroll 1
    for (; e + 6 < end; e += 8) {
        int s0 = g_csr[e];
        int s1 = g_csr[e + 2];
        int s2 = g_csr[e + 4];
        int s3 = g_csr[e + 6];
        float4 v0 = x4[(size_t)s0 * 16 + li];
        float4 v1 = x4[(size_t)s1 * 16 + li];
        float4 v2 = x4[(size_t)s2 * 16 + li];
        float4 v3 = x4[(size_t)s3 * 16 + li];
        acc.x += (v0.x + v1.x) + (v2.x + v3.x);
        acc.y += (v0.y + v1.y) + (v2.y + v3.y);
        acc.z += (v0.z + v1.z) + (v2.z + v3.z);
        acc.w += (v0.w + v1.w) + (v2.w + v3.w);
    }
    #pragma unroll 1
    for (; e < end; e += 2) {
        int s = g_csr[e];
        float4 v = x4[(size_t)s * 16 + li];
        acc.x += v.x; acc.y += v.y; acc.z += v.z; acc.w += v.w;
    }
    acc.x += __shfl_xor_sync(0xFFFFFFFFu, acc.x, 16);
    acc.y += __shfl_xor_sync(0xFFFFFFFFu, acc.y, 16);
    acc.z += __shfl_xor_sync(0xFFFFFFFFu, acc.z, 16);
    acc.w += __shfl_xor_sync(0xFFFFFFFFu, acc.w, 16);
    if (half == 0) {
        int d = end - beg;
        float inv = d > 0 ? 1.f / (float)d : 0.f;
        acc.x *= inv; acc.y *= inv; acc.z *= inv; acc.w *= inv;
        ((float4*)g_agg)[(size_t)gw * 16 + li] = acc;
    }
}

// ---------------- bf16 3-term split GEMM with register-prefetch pipeline ----------------
// Main: out = relu([agg | A1] @ [B0;B1] + bias). Block 256 thr, tile 128 x 64.
// Pipeline: sync -> split+store smem(kt) -> sync -> issue global loads(kt+1) -> mma(kt).
// If FUSE_FIN: re-split relu'd fragments into smem and run h @ Wfin + bfin directly.
template <bool FUSE_FIN>
__global__ void __launch_bounds__(256)
k_gemm(const float* __restrict__ xext, int asel, int dsel,
       const float* __restrict__ B0, const float* __restrict__ B1,
       const float* __restrict__ bias,
       const float* __restrict__ Wfin, const float* __restrict__ bfin,
       float* __restrict__ oext) {
    constexpr int BM   = 128;
    constexpr int LDAP = 136;
    constexpr int LDBP = 72;
    constexpr int MAIN_SZ = 2 * 16 * LDAP + 2 * 16 * LDBP;
    constexpr int FIN_SZ  = 2 * 32 * LDAP + 2 * 32 * 40;
    constexpr int BUF_SZ  = FUSE_FIN ? (FIN_SZ > MAIN_SZ ? FIN_SZ : MAIN_SZ) : MAIN_SZ;
    __shared__ uint32_t buf[BUF_SZ];

    uint32_t (*Ahp)[LDAP] = (uint32_t(*)[LDAP])(buf);
    uint32_t (*Alp)[LDAP] = (uint32_t(*)[LDAP])(buf + 16 * LDAP);
    uint32_t (*Bhp)[LDBP] = (uint32_t(*)[LDBP])(buf + 2 * 16 * LDAP);
    uint32_t (*Blp)[LDBP] = (uint32_t(*)[LDBP])(buf + 2 * 16 * LDAP + 16 * LDBP);

    const float* __restrict__ A1 = sel_buf(asel, xext);
    const float* __restrict__ A0 = (const float*)g_agg;
    float* __restrict__ out = FUSE_FIN ? oext : (dsel == 1 ? g_h0 : g_h1);

    const int t     = threadIdx.x;
    const int lane  = t & 31;
    const int wid   = t >> 5;
    const int g     = lane >> 2;
    const int tg    = lane & 3;
    const int mbase = blockIdx.x * BM;
    const int ma    = wid * 16 + g;

    // per-thread staging assignment (fixed across tiles)
    const int arow = t >> 1;             // A: 2 threads per row, each 8 k2 -> idx = t + i*256
    const int brow = t >> 6;

    float2 va[8];
    float2 vb[4];

    // global load of tile kt into registers
    auto load_tile = [&](int kt) {
        const bool second = (kt >= 64);
        const float* __restrict__ Asrc = second ? A1 : A0;
        const float* __restrict__ Bsrc = second ? B1 : B0;
        const int kb = second ? (kt - 64) : kt;
        #pragma unroll
        for (int i = 0; i < 8; i++) {
            int idx = t + i * 256;
            int row = idx >> 4;
            int k2  = idx & 15;
            int grow = mbase + row;
            va[i] = (grow < NN) ? *(const float2*)&Asrc[(size_t)grow * 64 + kb + 2 * k2]
                                : make_float2(0.f, 0.f);
        }
        #pragma unroll
        for (int i = 0; i < 4; i++) {
            int idx = t + i * 256;
            int k2 = idx >> 6;
            int cc = idx & 63;
            vb[i].x = Bsrc[(size_t)(kb + 2 * k2) * 64 + cc];
            vb[i].y = Bsrc[(size_t)(kb + 2 * k2 + 1) * 64 + cc];
        }
    };

    float c[8][4];
    #pragma unroll
    for (int nt = 0; nt < 8; nt++)
        #pragma unroll
        for (int i = 0; i < 4; i++) c[nt][i] = 0.f;

    load_tile(0);

    #pragma unroll 1
    for (int kt = 0; kt < 128; kt += 32) {
        // store current regs -> smem (split)
        #pragma unroll
        for (int i = 0; i < 8; i++) {
            int idx = t + i * 256;
            int row = idx >> 4;
            int k2  = idx & 15;
            uint32_t hp, lp;
            split_pack2(va[i].x, va[i].y, hp, lp);
            Ahp[k2][row] = hp;
            Alp[k2][row] = lp;
        }
        #pragma unroll
        for (int i = 0; i < 4; i++) {
            int idx = t + i * 256;
            int k2 = idx >> 6;
            int cc = idx & 63;
            uint32_t hp, lp;
            split_pack2(vb[i].x, vb[i].y, hp, lp);
            Bhp[k2][cc] = hp;
            Blp[k2][cc] = lp;
        }
        __syncthreads();

        // prefetch next tile while mma runs
        if (kt + 32 < 128) load_tile(kt + 32);

        #pragma unroll
        for (int ks = 0; ks < 2; ks++) {
            const int kk = ks * 8 + tg;
            uint32_t ah[4], al[4];
            ah[0] = Ahp[kk][ma];      ah[1] = Ahp[kk][ma + 8];
            ah[2] = Ahp[kk + 4][ma];  ah[3] = Ahp[kk + 4][ma + 8];
            al[0] = Alp[kk][ma];      al[1] = Alp[kk][ma + 8];
            al[2] = Alp[kk + 4][ma];  al[3] = Alp[kk + 4][ma + 8];
            #pragma unroll
            for (int nt = 0; nt < 8; nt++) {
                const int col = nt * 8 + g;
                uint32_t bh0 = Bhp[kk][col];
                uint32_t bh1 = Bhp[kk + 4][col];
                uint32_t bl0 = Blp[kk][col];
                uint32_t bl1 = Blp[kk + 4][col];
                mma_bf16(c[nt], al, bh0, bh1);
                mma_bf16(c[nt], ah, bl0, bl1);
                mma_bf16(c[nt], ah, bh0, bh1);
            }
        }
        __syncthreads();
    }
    (void)arow; (void)brow;

    const int r0 = mbase + wid * 16 + g;
    const int r1 = r0 + 8;

    if constexpr (!FUSE_FIN) {
        #pragma unroll
        for (int nt = 0; nt < 8; nt++) {
            const int col = nt * 8 + 2 * tg;
            float bx = bias[col];
            float by = bias[col + 1];
            if (r0 < NN) {
                float vx = fmaxf(c[nt][0] + bx, 0.f);
                float vy = fmaxf(c[nt][1] + by, 0.f);
                *(float2*)&out[(size_t)r0 * 64 + col] = make_float2(vx, vy);
            }
            if (r1 < NN) {
                float vx = fmaxf(c[nt][2] + bx, 0.f);
                float vy = fmaxf(c[nt][3] + by, 0.f);
                *(float2*)&out[(size_t)r1 * 64 + col] = make_float2(vx, vy);
            }
        }
    } else {
        uint32_t (*Fh)[LDAP] = (uint32_t(*)[LDAP])(buf);
        uint32_t (*Fl)[LDAP] = (uint32_t(*)[LDAP])(buf + 32 * LDAP);
        uint32_t (*B2h)[40]  = (uint32_t(*)[40])(buf + 2 * 32 * LDAP);
        uint32_t (*B2l)[40]  = (uint32_t(*)[40])(buf + 2 * 32 * LDAP + 32 * 40);

        const int rl0 = wid * 16 + g;
        const int rl1 = rl0 + 8;
        #pragma unroll
        for (int nt = 0; nt < 8; nt++) {
            const int col = nt * 8 + 2 * tg;
            const int k2  = nt * 4 + tg;
            float bx = bias[col];
            float by = bias[col + 1];
            float v0x = fmaxf(c[nt][0] + bx, 0.f);
            float v0y = fmaxf(c[nt][1] + by, 0.f);
            float v1x = fmaxf(c[nt][2] + bx, 0.f);
            float v1y = fmaxf(c[nt][3] + by, 0.f);
            uint32_t hp, lp;
            split_pack2(v0x, v0y, hp, lp);
            Fh[k2][rl0] = hp;
            Fl[k2][rl0] = lp;
            split_pack2(v1x, v1y, hp, lp);
            Fh[k2][rl1] = hp;
            Fl[k2][rl1] = lp;
        }
        #pragma unroll
        for (int idx = t; idx < 32 * 32; idx += 256) {
            int k2 = idx >> 5;
            int cc = idx & 31;
            float w0 = Wfin[(size_t)(2 * k2) * 32 + cc];
            float w1 = Wfin[(size_t)(2 * k2 + 1) * 32 + cc];
            uint32_t hp, lp;
            split_pack2(w0, w1, hp, lp);
            B2h[k2][cc] = hp;
            B2l[k2][cc] = lp;
        }
        __syncthreads();

        float c2[4][4];
        #pragma unroll
        for (int nt = 0; nt < 4; nt++)
            #pragma unroll
            for (int i = 0; i < 4; i++) c2[nt][i] = 0.f;

        #pragma unroll
        for (int ks = 0; ks < 4; ks++) {
            const int kk = ks * 8 + tg;
            uint32_t ah[4], al[4];
            ah[0] = Fh[kk][ma];      ah[1] = Fh[kk][ma + 8];
            ah[2] = Fh[kk + 4][ma];  ah[3] = Fh[kk + 4][ma + 8];
            al[0] = Fl[kk][ma];      al[1] = Fl[kk][ma + 8];
            al[2] = Fl[kk + 4][ma];  al[3] = Fl[kk + 4][ma + 8];
            #pragma unroll
            for (int nt = 0; nt < 4; nt++) {
                const int col = nt * 8 + g;
                uint32_t bh0 = B2h[kk][col];
                uint32_t bh1 = B2h[kk + 4][col];
                uint32_t bl0 = B2l[kk][col];
                uint32_t bl1 = B2l[kk + 4][col];
                mma_bf16(c2[nt], al, bh0, bh1);
                mma_bf16(c2[nt], ah, bl0, bl1);
                mma_bf16(c2[nt], ah, bh0, bh1);
            }
        }

        #pragma unroll
        for (int nt = 0; nt < 4; nt++) {
            const int col = nt * 8 + 2 * tg;
            float bx = bfin[col];
            float by = bfin[col + 1];
            if (r0 < NN)
                *(float2*)&out[(size_t)r0 * 32 + col] = make_float2(c2[nt][0] + bx, c2[nt][1] + by);
            if (r1 < NN)
                *(float2*)&out[(size_t)r1 * 32 + col] = make_float2(c2[nt][2] + bx, c2[nt][3] + by);
        }
    }
}

// ---------------- host launcher (pure kernel launches; graph-capturable) ----------------
extern "C" void kernel_launch(void* const* d_in, const int* in_sizes, int n_in,
                              void* d_out, int out_size) {
    const float* x    = (const float*)d_in[0];
    const int*   ei   = (const int*)d_in[1];
    const float* Wl1  = (const float*)d_in[2];
    const float* Wr1  = (const float*)d_in[3];
    const float* b1   = (const float*)d_in[4];
    const float* Wl2  = (const float*)d_in[5];
    const float* Wr2  = (const float*)d_in[6];
    const float* b2   = (const float*)d_in[7];
    const float* Wl3  = (const float*)d_in[8];
    const float* Wr3  = (const float*)d_in[9];
    const float* b3   = (const float*)d_in[10];
    const float* Wlin = (const float*)d_in[11];
    const float* blin = (const float*)d_in[12];
    float*       out  = (float*)d_out;

    // CSR build
    k_zero_deg<<<CDIV(NN, 256), 256>>>();
    k_count_pos<<<CDIV(NE, 256), 256>>>(ei);
    k_blocksum<<<NPART, SCAN_BS>>>();
    k_offsets<<<NPART, SCAN_BS>>>();
    k_scatter2<<<CDIV(NE, 256), 256>>>(ei);

    const int AGG_BLOCKS  = CDIV(NN, 8);
    const int GEMM_BLOCKS = CDIV(NN, 128);

    // layer 1: x -> h0
    k_agg<<<AGG_BLOCKS, 256>>>(x, 0);
    k_gemm<false><<<GEMM_BLOCKS, 256>>>(x, 0, 1, Wl1, Wr1, b1, nullptr, nullptr, nullptr);
    // layer 2: h0 -> h1
    k_agg<<<AGG_BLOCKS, 256>>>(nullptr, 1);
    k_gemm<false><<<GEMM_BLOCKS, 256>>>(nullptr, 1, 2, Wl2, Wr2, b2, nullptr, nullptr, nullptr);
    // layer 3 + final linear fused: h1 -> out
    k_agg<<<AGG_BLOCKS, 256>>>(nullptr, 2);
    k_gemm<true><<<GEMM_BLOCKS, 256>>>(nullptr, 2, 0, Wl3, Wr3, b3, Wlin, blin, out);
}